// round 6
// baseline (speedup 1.0000x reference)
#include <cuda_runtime.h>
#include <math.h>

#define B_ 64
#define F_ 256
#define T_ 1024
#define H_ 1024
#define O_ 512

#define NB   128          // persistent blocks: 4 groups (bt) x 32 (ht)
#define THR  256          // threads per block (2 warps / SMSP)
#define BT   16           // b rows per block
#define HT2  32           // h cols per block
#define KC   256          // k chunk staged in smem
#define WPAD 4
#define SPAD 4

#define WROW (H_ + WPAD)          // 1028 floats
#define SROW (KC + SPAD)          // 260 floats
#define NCH  (H_ / KC)            // 4 chunks
#define SMEM_RNN ((HT2 * WROW + 2 * BT * SROW) * 4)   // 164,864 B

// Scratch: buf[t][b][h]. xb before step t, state s_t after (in place).
__device__ float g_buf[(size_t)T_ * B_ * H_];   // 256 MB
__device__ unsigned g_flags[NB];                // per-block arrival flags
__device__ unsigned g_relG[4 * 32];             // per-group release (padded)

// ---------------------------------------------------------------------------
// Group barrier (32 blocks sharing bt). Members: store flag, poll release.
// Leader (ht==0): one warp scans the 31 member flags, then releases.
// Monotonic epochs -> safe across graph replays. bar.sync + fence.gpu by one
// thread is cumulative (PTX mem model), and the fence's CCTL.IVALL refreshes
// this SM's L1D for the cross-SM state reads.
// ---------------------------------------------------------------------------
__device__ __forceinline__ void gsync(int bt, int ht, unsigned target) {
    __syncthreads();
    if (ht == 0) {
        unsigned i = threadIdx.x;
        if (i >= 1 && i < 32) {
            while ((int)(*(volatile unsigned*)&g_flags[bt * 32 + i] - target) < 0)
                __nanosleep(20);
        }
        __syncthreads();
        if (threadIdx.x == 0) {
            __threadfence();
            *(volatile unsigned*)&g_relG[bt * 32] = target;
        }
        __syncthreads();
    } else {
        if (threadIdx.x == 0) {
            __threadfence();   // order this block's stores before its flag
            *(volatile unsigned*)&g_flags[bt * 32 + ht] = target;
            while ((int)(*(volatile unsigned*)&g_relG[bt * 32] - target) < 0)
                __nanosleep(20);
            __threadfence();   // acquire + L1D refresh
        }
        __syncthreads();
    }
}

// ---------------------------------------------------------------------------
// Kernel 1: buf[t][b][h] = bias[h] + sum_f x[b][f][t] * Wx[f][h]
// ---------------------------------------------------------------------------
__global__ __launch_bounds__(256) void k_xw(const float* __restrict__ x,
                                            const float* __restrict__ Wx,
                                            const float* __restrict__ bias) {
    const int BM = 128, BN = 128, BK = 8;
    __shared__ float As[BK][BM];
    __shared__ float Bs[BK][BN];

    int tid = threadIdx.x;
    int tx = tid % 16, ty = tid / 16;
    int n0 = blockIdx.x * BN;
    int mtile = blockIdx.y;
    int b  = mtile / (T_ / BM);
    int t0 = (mtile % (T_ / BM)) * BM;

    float acc[8][8];
#pragma unroll
    for (int i = 0; i < 8; i++)
#pragma unroll
        for (int j = 0; j < 8; j++) acc[i][j] = 0.f;

    const float* xb = x + (size_t)b * F_ * T_ + t0;

    for (int kc = 0; kc < F_; kc += BK) {
#pragma unroll
        for (int i = 0; i < 4; i++) {
            int e = i * 256 + tid;
            int mm = e % BM, kk = e / BM;
            As[kk][mm] = xb[(size_t)(kc + kk) * T_ + mm];
        }
#pragma unroll
        for (int i = 0; i < 4; i++) {
            int e = i * 256 + tid;
            int nn = e % BN, kk = e / BN;
            Bs[kk][nn] = Wx[(size_t)(kc + kk) * H_ + n0 + nn];
        }
        __syncthreads();
#pragma unroll
        for (int k = 0; k < BK; k++) {
            float ra[8], rb[8];
#pragma unroll
            for (int i = 0; i < 8; i++) ra[i] = As[k][ty + 16 * i];
#pragma unroll
            for (int j = 0; j < 8; j++) rb[j] = Bs[k][tx + 16 * j];
#pragma unroll
            for (int i = 0; i < 8; i++)
#pragma unroll
                for (int j = 0; j < 8; j++) acc[i][j] += ra[i] * rb[j];
        }
        __syncthreads();
    }

#pragma unroll
    for (int i = 0; i < 8; i++) {
        int t = t0 + ty + 16 * i;
        float* dst = g_buf + ((size_t)t * B_ + b) * H_ + n0;
#pragma unroll
        for (int j = 0; j < 8; j++) {
            int n = tx + 16 * j;
            dst[n] = acc[i][j] + bias[n0 + n];
        }
    }
}

// ---------------------------------------------------------------------------
// Kernel 2: persistent recurrence. Block (bt, ht): C[16 b][32 h], full K.
// Wh slice transposed+resident in smem (128 KB). 256 threads, 2b x 1h tile.
// One 32-block group barrier per step.
// ---------------------------------------------------------------------------
__global__ __launch_bounds__(THR, 1) void k_rnn(const float* __restrict__ Wh) {
    extern __shared__ float smem[];
    float* sWh = smem;                      // [HT2][WROW]
    float* sS  = smem + HT2 * WROW;         // [2][BT][SROW]

    const int tid = threadIdx.x;
    const int bx  = blockIdx.x;
    const int bt  = bx >> 5;                // 0..3  (b group)
    const int ht  = bx & 31;                // 0..31 (h tile)
    const int b0  = bt * BT;
    const int h0  = ht * HT2;
    const int bIdx = tid & 7;               // rows bIdx, bIdx+8
    const int hIdx = tid >> 3;              // 0..31, one h col

    // Load Wh slice once, transposed: sWh[h][k] = Wh[k][h0+h]
    for (int i = tid; i < HT2 * H_ / 4; i += THR) {
        int k  = i >> 3;
        int hq = (i & 7) * 4;
        float4 v = *reinterpret_cast<const float4*>(&Wh[(size_t)k * H_ + h0 + hq]);
        sWh[(size_t)(hq + 0) * WROW + k] = v.x;
        sWh[(size_t)(hq + 1) * WROW + k] = v.y;
        sWh[(size_t)(hq + 2) * WROW + k] = v.z;
        sWh[(size_t)(hq + 3) * WROW + k] = v.w;
    }
    __syncthreads();

    const float* wRow = &sWh[(size_t)hIdx * WROW];

    unsigned base = *(volatile unsigned*)&g_relG[bt * 32];
    unsigned bar = 0;

    const int gb0 = b0 + bIdx, gb1 = b0 + bIdx + 8;
    const int gh  = h0 + hIdx;

    for (int t = 0; t < T_; ++t) {
        float* cur = g_buf + (size_t)t * B_ * H_;

        // prefetch xb for this thread's 2 outputs (overlaps the GEMM)
        float xb0 = cur[(size_t)gb0 * H_ + gh];
        float xb1 = cur[(size_t)gb1 * H_ + gh];

        float a0 = 0.f, a1 = 0.f;

        if (t > 0) {
            const float* sp = g_buf + (size_t)(t - 1) * B_ * H_ + (size_t)b0 * H_;

            // preload chunk 0 into registers (16 rows x 256 k = 1024 float4)
            float4 pv[4];
#pragma unroll
            for (int it = 0; it < 4; it++) {
                int idx = it * THR + tid;
                int row = idx >> 6, q = idx & 63;
                pv[it] = *reinterpret_cast<const float4*>(
                    &sp[(size_t)row * H_ + q * 4]);
            }

            for (int c = 0; c < NCH; ++c) {
                float* sb = sS + (c & 1) * (BT * SROW);
                __syncthreads();
#pragma unroll
                for (int it = 0; it < 4; it++) {
                    int idx = it * THR + tid;
                    int row = idx >> 6, q = idx & 63;
                    *reinterpret_cast<float4*>(&sb[row * SROW + q * 4]) = pv[it];
                }
                __syncthreads();
                if (c + 1 < NCH) {
                    const float* spn = sp + (c + 1) * KC;
#pragma unroll
                    for (int it = 0; it < 4; it++) {
                        int idx = it * THR + tid;
                        int row = idx >> 6, q = idx & 63;
                        pv[it] = *reinterpret_cast<const float4*>(
                            &spn[(size_t)row * H_ + q * 4]);
                    }
                }
                const float* s0r = &sb[bIdx * SROW];
                const float* s1r = &sb[(bIdx + 8) * SROW];
                const float* wr  = wRow + c * KC;
#pragma unroll 8
                for (int q = 0; q < KC / 4; q++) {
                    float4 s0 = *reinterpret_cast<const float4*>(&s0r[q * 4]);
                    float4 s1 = *reinterpret_cast<const float4*>(&s1r[q * 4]);
                    float4 w  = *reinterpret_cast<const float4*>(&wr[q * 4]);
                    a0 += s0.x * w.x; a1 += s1.x * w.x;
                    a0 += s0.y * w.y; a1 += s1.y * w.y;
                    a0 += s0.z * w.z; a1 += s1.z * w.z;
                    a0 += s0.w * w.w; a1 += s1.w * w.w;
                }
            }
        }

        // epilogue: s_t = tanh(xb + acc), in place
        cur[(size_t)gb0 * H_ + gh] = tanhf(xb0 + a0);
        cur[(size_t)gb1 * H_ + gh] = tanhf(xb1 + a1);

        gsync(bt, ht, base + (++bar));
    }
}

// ---------------------------------------------------------------------------
// Kernel 3: out[b][t][o] = bout[o] + sum_h buf[t][b][h] * Wout[h][o]
// ---------------------------------------------------------------------------
__global__ __launch_bounds__(256) void k_out(const float* __restrict__ Wout,
                                             const float* __restrict__ bout,
                                             float* __restrict__ out) {
    const int BM = 128, BN = 128, BK = 8;
    __shared__ float As[BK][BM + 4];
    __shared__ float Bs[BK][BN];

    int tid = threadIdx.x;
    int tx = tid % 16, ty = tid / 16;
    int n0 = blockIdx.x * BN;
    int m0 = blockIdx.y * BM;

    float acc[8][8];
#pragma unroll
    for (int i = 0; i < 8; i++)
#pragma unroll
        for (int j = 0; j < 8; j++) acc[i][j] = 0.f;

    const float* A = g_buf;  // [m][k], m = t*B + b, K = H_

    for (int kc = 0; kc < H_; kc += BK) {
        {
            int mm = tid >> 1;
            int kq = (tid & 1) * 4;
            float4 v = *reinterpret_cast<const float4*>(
                &A[(size_t)(m0 + mm) * H_ + kc + kq]);
            As[kq + 0][mm] = v.x;
            As[kq + 1][mm] = v.y;
            As[kq + 2][mm] = v.z;
            As[kq + 3][mm] = v.w;
        }
#pragma unroll
        for (int i = 0; i < 4; i++) {
            int e = i * 256 + tid;
            int nn = e % BN, kk = e / BN;
            Bs[kk][nn] = Wout[(size_t)(kc + kk) * O_ + n0 + nn];
        }
        __syncthreads();
#pragma unroll
        for (int k = 0; k < BK; k++) {
            float ra[8], rb[8];
#pragma unroll
            for (int i = 0; i < 8; i++) ra[i] = As[k][ty + 16 * i];
#pragma unroll
            for (int j = 0; j < 8; j++) rb[j] = Bs[k][tx + 16 * j];
#pragma unroll
            for (int i = 0; i < 8; i++)
#pragma unroll
                for (int j = 0; j < 8; j++) acc[i][j] += ra[i] * rb[j];
        }
        __syncthreads();
    }

#pragma unroll
    for (int i = 0; i < 8; i++) {
        int m = m0 + ty + 16 * i;
        int t = m / B_;
        int b = m % B_;
        float* dst = out + ((size_t)b * T_ + t) * O_ + n0;
#pragma unroll
        for (int j = 0; j < 8; j++) {
            int n = tx + 16 * j;
            dst[n] = acc[i][j] + bout[n0 + n];
        }
    }
}

extern "C" void kernel_launch(void* const* d_in, const int* in_sizes, int n_in,
                              void* d_out, int out_size) {
    const float* x    = (const float*)d_in[0];
    const float* Wx   = (const float*)d_in[1];
    const float* Wh   = (const float*)d_in[2];
    const float* bias = (const float*)d_in[3];
    const float* Wout = (const float*)d_in[4];
    const float* bout = (const float*)d_in[5];
    float* out = (float*)d_out;

    (void)in_sizes; (void)n_in; (void)out_size;

    cudaFuncSetAttribute(k_rnn, cudaFuncAttributeMaxDynamicSharedMemorySize,
                         SMEM_RNN);

    dim3 g1(H_ / 128, (B_ * T_) / 128);   // (8, 512)
    k_xw<<<g1, 256>>>(x, Wx, bias);

    k_rnn<<<NB, THR, SMEM_RNN>>>(Wh);     // single persistent launch

    dim3 g3(O_ / 128, (B_ * T_) / 128);   // (4, 512)
    k_out<<<g3, 256>>>(Wout, bout, out);
}

// round 7
// speedup vs baseline: 1.0735x; 1.0735x over previous
#include <cuda_runtime.h>
#include <math.h>

#define B_ 64
#define F_ 256
#define T_ 1024
#define H_ 1024
#define O_ 512

#define NB   128          // persistent blocks: 4 groups (bt) x 32 (ht)
#define BT   16           // b rows per block
#define HT2  32           // h cols per block
#define KC   128          // k chunk staged in smem
#define WPAD 4
#define SPAD 4

#define WROW (H_ + WPAD)          // 1028 floats
#define SROW (KC + SPAD)          // 132 floats
#define SMEM_RNN ((HT2 * WROW + 2 * BT * SROW) * 4)   // 148,480 B

// Scratch: buf[t][b][h]. xb before step t, state s_t after (in place).
__device__ float g_buf[(size_t)T_ * B_ * H_];   // 256 MB
__device__ unsigned g_flags[NB];                // per-block step counters

// ---------------------------------------------------------------------------
// Direct-scan group barrier: the 32 blocks sharing bt sync among themselves.
// Every block stores its own flag, then 32 threads scan the group's 32 flags
// (one 128B L2 line). No leader/release indirection -> one L2 round trip.
// Monotonic epochs -> safe across graph replays. Final fence (gpu scope)
// emits CCTL.IVALL, refreshing this SM's L1D for cross-SM state reads.
// ---------------------------------------------------------------------------
__device__ __forceinline__ void gsync(int bt, unsigned target) {
    __syncthreads();                         // all block stores issued
    if (threadIdx.x == 0) {
        __threadfence();                     // order stores before flag
        *(volatile unsigned*)&g_flags[blockIdx.x] = target;
    }
    if (threadIdx.x < 32) {
        while ((int)(*(volatile unsigned*)&g_flags[bt * 32 + threadIdx.x]
                     - target) < 0)
            __nanosleep(20);
    }
    __syncthreads();                         // all 32 flags confirmed
    if (threadIdx.x == 0) __threadfence();   // acquire + L1D refresh
    __syncthreads();
}

// ---------------------------------------------------------------------------
// Kernel 1: buf[t][b][h] = bias[h] + sum_f x[b][f][t] * Wx[f][h]
// Ping-pong smem, one __syncthreads per k-iter, LDG staged through registers.
// ---------------------------------------------------------------------------
__global__ __launch_bounds__(256) void k_xw(const float* __restrict__ x,
                                            const float* __restrict__ Wx,
                                            const float* __restrict__ bias) {
    const int BM = 128, BN = 128, BK = 8, NC = F_ / BK;
    __shared__ float As[2][BK][BM];
    __shared__ float Bs[2][BK][BN];

    int tid = threadIdx.x;
    int tx = tid % 16, ty = tid / 16;
    int n0 = blockIdx.x * BN;
    int mtile = blockIdx.y;
    int b  = mtile / (T_ / BM);
    int t0 = (mtile % (T_ / BM)) * BM;

    const float* xb = x + (size_t)b * F_ * T_ + t0;

    const int lk = tid >> 5;          // 0..7
    const int lq = (tid & 31) * 4;    // 0..124

    float4 ra = *reinterpret_cast<const float4*>(&xb[(size_t)lk * T_ + lq]);
    float4 rb = *reinterpret_cast<const float4*>(&Wx[(size_t)lk * H_ + n0 + lq]);
    *reinterpret_cast<float4*>(&As[0][lk][lq]) = ra;
    *reinterpret_cast<float4*>(&Bs[0][lk][lq]) = rb;
    __syncthreads();

    float acc[8][8];
#pragma unroll
    for (int i = 0; i < 8; i++)
#pragma unroll
        for (int j = 0; j < 8; j++) acc[i][j] = 0.f;

    for (int c = 0; c < NC; ++c) {
        int cur = c & 1;
        if (c + 1 < NC) {
            ra = *reinterpret_cast<const float4*>(
                &xb[(size_t)((c + 1) * BK + lk) * T_ + lq]);
            rb = *reinterpret_cast<const float4*>(
                &Wx[(size_t)((c + 1) * BK + lk) * H_ + n0 + lq]);
        }
#pragma unroll
        for (int k = 0; k < BK; k++) {
            float va[8], vb[8];
#pragma unroll
            for (int i = 0; i < 8; i++) va[i] = As[cur][k][ty + 16 * i];
#pragma unroll
            for (int j = 0; j < 8; j++) vb[j] = Bs[cur][k][tx + 16 * j];
#pragma unroll
            for (int i = 0; i < 8; i++)
#pragma unroll
                for (int j = 0; j < 8; j++) acc[i][j] += va[i] * vb[j];
        }
        if (c + 1 < NC) {
            *reinterpret_cast<float4*>(&As[1 - cur][lk][lq]) = ra;
            *reinterpret_cast<float4*>(&Bs[1 - cur][lk][lq]) = rb;
            __syncthreads();
        }
    }

#pragma unroll
    for (int i = 0; i < 8; i++) {
        int t = t0 + ty + 16 * i;
        float* dst = g_buf + ((size_t)t * B_ + b) * H_ + n0;
#pragma unroll
        for (int j = 0; j < 8; j++) {
            int n = tx + 16 * j;
            dst[n] = acc[i][j] + bias[n0 + n];
        }
    }
}

// ---------------------------------------------------------------------------
// Kernel 2: persistent recurrence (PROVEN R3 compute). Block (bt, ht):
// C[16 b][32 h] over full K=1024. Wh slice transposed+resident in smem
// (128 KB). 128 threads, 2b x 2h thread tile. One group barrier per step.
// ---------------------------------------------------------------------------
__global__ __launch_bounds__(128, 1) void k_rnn(const float* __restrict__ Wh) {
    extern __shared__ float smem[];
    float* sWh = smem;                      // [HT2][WROW]
    float* sS  = smem + HT2 * WROW;         // [2][BT][SROW]

    const int tid = threadIdx.x;
    const int bx  = blockIdx.x;
    const int bt  = bx >> 5;                // 0..3
    const int ht  = bx & 31;                // 0..31
    const int b0  = bt * BT;
    const int h0  = ht * HT2;
    const int hIdx = tid & 15;              // h, h+16
    const int bIdx = tid >> 4;              // b, b+8   (0..7)

    // Load Wh slice once, transposed: sWh[h][k] = Wh[k][h0+h]
    for (int i = tid; i < HT2 * H_ / 4; i += 128) {
        int k  = i >> 3;
        int hq = (i & 7) * 4;
        float4 v = *reinterpret_cast<const float4*>(&Wh[(size_t)k * H_ + h0 + hq]);
        sWh[(size_t)(hq + 0) * WROW + k] = v.x;
        sWh[(size_t)(hq + 1) * WROW + k] = v.y;
        sWh[(size_t)(hq + 2) * WROW + k] = v.z;
        sWh[(size_t)(hq + 3) * WROW + k] = v.w;
    }
    __syncthreads();

    const float* sW0 = &sWh[(size_t)hIdx * WROW];
    const float* sW1 = &sWh[(size_t)(hIdx + 16) * WROW];

    unsigned base = *(volatile unsigned*)&g_flags[bx];
    unsigned bar = 0;

    const int gb0 = b0 + bIdx, gb1 = b0 + bIdx + 8;
    const int gh0 = h0 + hIdx, gh1 = h0 + hIdx + 16;

    for (int t = 0; t < T_; ++t) {
        float* cur = g_buf + (size_t)t * B_ * H_;

        // prefetch xb for this thread's outputs (hides latency behind GEMM)
        float xb00 = cur[(size_t)gb0 * H_ + gh0];
        float xb01 = cur[(size_t)gb0 * H_ + gh1];
        float xb10 = cur[(size_t)gb1 * H_ + gh0];
        float xb11 = cur[(size_t)gb1 * H_ + gh1];

        float a00 = 0.f, a01 = 0.f, a10 = 0.f, a11 = 0.f;

        if (t > 0) {
            const float* sp = g_buf + (size_t)(t - 1) * B_ * H_ + (size_t)b0 * H_;

            // preload chunk 0 into registers
            float4 pv[4];
#pragma unroll
            for (int it = 0; it < 4; it++) {
                int idx = it * 128 + tid;
                int row = idx >> 5, q = idx & 31;
                pv[it] = *reinterpret_cast<const float4*>(
                    &sp[(size_t)row * H_ + q * 4]);
            }

            for (int c = 0; c < H_ / KC; ++c) {
                float* sb = sS + (c & 1) * (BT * SROW);
                __syncthreads();
#pragma unroll
                for (int it = 0; it < 4; it++) {
                    int idx = it * 128 + tid;
                    int row = idx >> 5, q = idx & 31;
                    *reinterpret_cast<float4*>(&sb[row * SROW + q * 4]) = pv[it];
                }
                __syncthreads();
                if (c + 1 < H_ / KC) {
                    const float* spn = sp + (c + 1) * KC;
#pragma unroll
                    for (int it = 0; it < 4; it++) {
                        int idx = it * 128 + tid;
                        int row = idx >> 5, q = idx & 31;
                        pv[it] = *reinterpret_cast<const float4*>(
                            &spn[(size_t)row * H_ + q * 4]);
                    }
                }
                const float* s0r = &sb[bIdx * SROW];
                const float* s1r = &sb[(bIdx + 8) * SROW];
                const float* w0r = sW0 + c * KC;
                const float* w1r = sW1 + c * KC;
#pragma unroll 8
                for (int q = 0; q < KC / 4; q++) {
                    float4 s0 = *reinterpret_cast<const float4*>(&s0r[q * 4]);
                    float4 s1 = *reinterpret_cast<const float4*>(&s1r[q * 4]);
                    float4 w0 = *reinterpret_cast<const float4*>(&w0r[q * 4]);
                    float4 w1 = *reinterpret_cast<const float4*>(&w1r[q * 4]);
                    a00 += s0.x * w0.x; a01 += s0.x * w1.x;
                    a10 += s1.x * w0.x; a11 += s1.x * w1.x;
                    a00 += s0.y * w0.y; a01 += s0.y * w1.y;
                    a10 += s1.y * w0.y; a11 += s1.y * w1.y;
                    a00 += s0.z * w0.z; a01 += s0.z * w1.z;
                    a10 += s1.z * w0.z; a11 += s1.z * w1.z;
                    a00 += s0.w * w0.w; a01 += s0.w * w1.w;
                    a10 += s1.w * w0.w; a11 += s1.w * w1.w;
                }
            }
        }

        // epilogue: s_t = tanh(xb + acc), in place
        cur[(size_t)gb0 * H_ + gh0] = tanhf(xb00 + a00);
        cur[(size_t)gb0 * H_ + gh1] = tanhf(xb01 + a01);
        cur[(size_t)gb1 * H_ + gh0] = tanhf(xb10 + a10);
        cur[(size_t)gb1 * H_ + gh1] = tanhf(xb11 + a11);

        gsync(bt, base + (++bar));
    }
}

// ---------------------------------------------------------------------------
// Kernel 3: out[b][t][o] = bout[o] + sum_h buf[t][b][h] * Wout[h][o]
// Ping-pong smem, one __syncthreads per k-iter.
// ---------------------------------------------------------------------------
__global__ __launch_bounds__(256) void k_out(const float* __restrict__ Wout,
                                             const float* __restrict__ bout,
                                             float* __restrict__ out) {
    const int BM = 128, BN = 128, BK = 8, NC = H_ / BK;
    __shared__ float As[2][BK][BM + 4];
    __shared__ float Bs[2][BK][BN];

    int tid = threadIdx.x;
    int tx = tid % 16, ty = tid / 16;
    int n0 = blockIdx.x * BN;
    int m0 = blockIdx.y * BM;

    const float* A = g_buf;  // [m][k], m = t*B + b, K = H_

    const int mm = tid >> 1;            // A stage: row
    const int kq = (tid & 1) * 4;       // A stage: k quad
    const int lk = tid >> 5;            // B stage: k
    const int lq = (tid & 31) * 4;      // B stage: n quad

    float4 ra = *reinterpret_cast<const float4*>(&A[(size_t)(m0 + mm) * H_ + kq]);
    float4 rb = *reinterpret_cast<const float4*>(&Wout[(size_t)lk * O_ + n0 + lq]);
    As[0][kq + 0][mm] = ra.x;
    As[0][kq + 1][mm] = ra.y;
    As[0][kq + 2][mm] = ra.z;
    As[0][kq + 3][mm] = ra.w;
    *reinterpret_cast<float4*>(&Bs[0][lk][lq]) = rb;
    __syncthreads();

    float acc[8][8];
#pragma unroll
    for (int i = 0; i < 8; i++)
#pragma unroll
        for (int j = 0; j < 8; j++) acc[i][j] = 0.f;

    for (int c = 0; c < NC; ++c) {
        int cur = c & 1;
        if (c + 1 < NC) {
            ra = *reinterpret_cast<const float4*>(
                &A[(size_t)(m0 + mm) * H_ + (c + 1) * BK + kq]);
            rb = *reinterpret_cast<const float4*>(
                &Wout[(size_t)((c + 1) * BK + lk) * O_ + n0 + lq]);
        }
#pragma unroll
        for (int k = 0; k < BK; k++) {
            float va[8], vb[8];
#pragma unroll
            for (int i = 0; i < 8; i++) va[i] = As[cur][k][ty + 16 * i];
#pragma unroll
            for (int j = 0; j < 8; j++) vb[j] = Bs[cur][k][tx + 16 * j];
#pragma unroll
            for (int i = 0; i < 8; i++)
#pragma unroll
                for (int j = 0; j < 8; j++) acc[i][j] += va[i] * vb[j];
        }
        if (c + 1 < NC) {
            As[1 - cur][kq + 0][mm] = ra.x;
            As[1 - cur][kq + 1][mm] = ra.y;
            As[1 - cur][kq + 2][mm] = ra.z;
            As[1 - cur][kq + 3][mm] = ra.w;
            *reinterpret_cast<float4*>(&Bs[1 - cur][lk][lq]) = rb;
            __syncthreads();
        }
    }

    // m = t*B + b  ->  out[(b*T + t)*O + n]
#pragma unroll
    for (int i = 0; i < 8; i++) {
        int m = m0 + ty + 16 * i;
        int t = m >> 6;          // / B_
        int b = m & 63;          // % B_
        float* dst = out + ((size_t)b * T_ + t) * O_ + n0;
#pragma unroll
        for (int j = 0; j < 8; j++) {
            int n = tx + 16 * j;
            dst[n] = acc[i][j] + bout[n0 + n];
        }
    }
}

extern "C" void kernel_launch(void* const* d_in, const int* in_sizes, int n_in,
                              void* d_out, int out_size) {
    const float* x    = (const float*)d_in[0];
    const float* Wx   = (const float*)d_in[1];
    const float* Wh   = (const float*)d_in[2];
    const float* bias = (const float*)d_in[3];
    const float* Wout = (const float*)d_in[4];
    const float* bout = (const float*)d_in[5];
    float* out = (float*)d_out;

    (void)in_sizes; (void)n_in; (void)out_size;

    cudaFuncSetAttribute(k_rnn, cudaFuncAttributeMaxDynamicSharedMemorySize,
                         SMEM_RNN);

    dim3 g1(H_ / 128, (B_ * T_) / 128);   // (8, 512)
    k_xw<<<g1, 256>>>(x, Wx, bias);

    k_rnn<<<NB, 128, SMEM_RNN>>>(Wh);     // single persistent launch

    dim3 g3(O_ / 128, (B_ * T_) / 128);   // (4, 512)
    k_out<<<g3, 256>>>(Wout, bout, out);
}

// round 8
// speedup vs baseline: 1.3125x; 1.2226x over previous
#include <cuda_runtime.h>
#include <math.h>

#define B_ 64
#define F_ 256
#define T_ 1024
#define H_ 1024
#define O_ 512

#define NB   128          // persistent blocks
#define BT   16           // b rows per block
#define HT2  32           // h cols per block (stored as 16 interleaved pairs)
#define KC   128          // k chunk staged in smem
#define SPAD 4

#define WROW2 (2 * H_ + 4)        // 2052 floats: interleaved (h, h+16) pairs
#define SROW (KC + SPAD)          // 132 floats
#define SMEM_RNN ((16 * WROW2 + 2 * BT * SROW) * 4)   // 148,224 B

// Scratch: buf[t][b][h]. xb before step t, state s_t after (in place).
__device__ float g_buf[(size_t)T_ * B_ * H_];   // 256 MB
__device__ unsigned g_flags[NB];                // barrier arrival flags
__device__ unsigned g_rel2;                     // barrier release (monotonic)

// ---------------------------------------------------------------------------
// PROVEN R3 barrier: distributed arrival flags, leader (block 0) scans with
// 128 threads, single release word polled by members. Monotonic epochs.
// ---------------------------------------------------------------------------
__device__ __forceinline__ void gsync(unsigned target) {
    __syncthreads();
    if (blockIdx.x == 0) {
        if (threadIdx.x == 0) {
            __threadfence();
            *(volatile unsigned*)&g_flags[0] = target;
        }
        unsigned i = threadIdx.x;       // 128 threads scan 128 flags
        while ((int)(*(volatile unsigned*)&g_flags[i] - target) < 0)
            __nanosleep(40);
        __syncthreads();
        if (threadIdx.x == 0) {
            __threadfence();
            *(volatile unsigned*)&g_rel2 = target;
        }
        __syncthreads();
    } else {
        if (threadIdx.x == 0) {
            __threadfence();            // order data before flag
            *(volatile unsigned*)&g_flags[blockIdx.x] = target;
            while ((int)(*(volatile unsigned*)&g_rel2 - target) < 0)
                __nanosleep(40);
            __threadfence();            // acquire + L1D refresh
        }
        __syncthreads();
    }
}

// ---- packed f32x2 helpers (sm_103a FFMA2 path; ptxas won't auto-fuse) ----
__device__ __forceinline__ unsigned long long pk2(float v) {
    unsigned long long r;
    asm("mov.b64 %0, {%1, %1};" : "=l"(r) : "f"(v));
    return r;
}
__device__ __forceinline__ void fma2(unsigned long long& a,
                                     unsigned long long x,
                                     unsigned long long y) {
    asm("fma.rn.f32x2 %0, %1, %2, %0;" : "+l"(a) : "l"(x), "l"(y));
}
__device__ __forceinline__ float2 unpk(unsigned long long v) {
    float2 f;
    asm("mov.b64 {%0, %1}, %2;" : "=f"(f.x), "=f"(f.y) : "l"(v));
    return f;
}

// ---------------------------------------------------------------------------
// Kernel 1: buf[t][b][h] = bias[h] + sum_f x[b][f][t] * Wx[f][h]
// Ping-pong smem, one __syncthreads per k-iter (measured 949us).
// ---------------------------------------------------------------------------
__global__ __launch_bounds__(256) void k_xw(const float* __restrict__ x,
                                            const float* __restrict__ Wx,
                                            const float* __restrict__ bias) {
    const int BM = 128, BN = 128, BK = 8, NC = F_ / BK;
    __shared__ float As[2][BK][BM];
    __shared__ float Bs[2][BK][BN];

    int tid = threadIdx.x;
    int tx = tid % 16, ty = tid / 16;
    int n0 = blockIdx.x * BN;
    int mtile = blockIdx.y;
    int b  = mtile / (T_ / BM);
    int t0 = (mtile % (T_ / BM)) * BM;

    const float* xb = x + (size_t)b * F_ * T_ + t0;

    const int lk = tid >> 5;
    const int lq = (tid & 31) * 4;

    float4 ra = *reinterpret_cast<const float4*>(&xb[(size_t)lk * T_ + lq]);
    float4 rb = *reinterpret_cast<const float4*>(&Wx[(size_t)lk * H_ + n0 + lq]);
    *reinterpret_cast<float4*>(&As[0][lk][lq]) = ra;
    *reinterpret_cast<float4*>(&Bs[0][lk][lq]) = rb;
    __syncthreads();

    float acc[8][8];
#pragma unroll
    for (int i = 0; i < 8; i++)
#pragma unroll
        for (int j = 0; j < 8; j++) acc[i][j] = 0.f;

    for (int c = 0; c < NC; ++c) {
        int cur = c & 1;
        if (c + 1 < NC) {
            ra = *reinterpret_cast<const float4*>(
                &xb[(size_t)((c + 1) * BK + lk) * T_ + lq]);
            rb = *reinterpret_cast<const float4*>(
                &Wx[(size_t)((c + 1) * BK + lk) * H_ + n0 + lq]);
        }
#pragma unroll
        for (int k = 0; k < BK; k++) {
            float va[8], vb[8];
#pragma unroll
            for (int i = 0; i < 8; i++) va[i] = As[cur][k][ty + 16 * i];
#pragma unroll
            for (int j = 0; j < 8; j++) vb[j] = Bs[cur][k][tx + 16 * j];
#pragma unroll
            for (int i = 0; i < 8; i++)
#pragma unroll
                for (int j = 0; j < 8; j++) acc[i][j] += va[i] * vb[j];
        }
        if (c + 1 < NC) {
            *reinterpret_cast<float4*>(&As[1 - cur][lk][lq]) = ra;
            *reinterpret_cast<float4*>(&Bs[1 - cur][lk][lq]) = rb;
            __syncthreads();
        }
    }

#pragma unroll
    for (int i = 0; i < 8; i++) {
        int t = t0 + ty + 16 * i;
        float* dst = g_buf + ((size_t)t * B_ + b) * H_ + n0;
#pragma unroll
        for (int j = 0; j < 8; j++) {
            int n = tx + 16 * j;
            dst[n] = acc[i][j] + bias[n0 + n];
        }
    }
}

// ---------------------------------------------------------------------------
// Kernel 2: persistent recurrence. Block bx = (bt, ht): C[16 b][32 h],
// full K=1024. Wh slice resident in smem, interleaved (h, h+16) pairs so the
// inner loop runs on packed fma.rn.f32x2 (2 FMA/lane/inst). 128 threads,
// 2b x 2h thread tile. R3 leader barrier once per step; xb prefetch for the
// next step is hoisted before the barrier (race-free: only this block writes
// its own tile of buf[t+1], and only at step t+1).
// ---------------------------------------------------------------------------
__global__ __launch_bounds__(128, 1) void k_rnn(const float* __restrict__ Wh) {
    extern __shared__ float smem[];
    float* sWh = smem;                      // [16][WROW2] interleaved pairs
    float* sS  = smem + 16 * WROW2;         // [2][BT][SROW]

    const int tid = threadIdx.x;
    const int bx  = blockIdx.x;
    const int bt  = bx >> 5;                // 0..3
    const int ht  = bx & 31;                // 0..31
    const int b0  = bt * BT;
    const int h0  = ht * HT2;
    const int hIdx = tid & 15;              // h cols hIdx, hIdx+16
    const int bIdx = tid >> 4;              // b rows bIdx, bIdx+8

    // Load Wh slice once, pair-interleaved:
    // sWh[hh][2k+0] = Wh[k][h0+hh], sWh[hh][2k+1] = Wh[k][h0+hh+16]
    for (int i = tid; i < 16 * H_; i += 128) {
        int hh = i & 15;
        int k  = i >> 4;
        sWh[(size_t)hh * WROW2 + 2 * k]     = Wh[(size_t)k * H_ + h0 + hh];
        sWh[(size_t)hh * WROW2 + 2 * k + 1] = Wh[(size_t)k * H_ + h0 + hh + 16];
    }
    __syncthreads();

    const float* wRow = &sWh[(size_t)hIdx * WROW2];

    unsigned base = *(volatile unsigned*)&g_rel2;
    unsigned bar = 0;

    const int gb0 = b0 + bIdx, gb1 = b0 + bIdx + 8;
    const int gh0 = h0 + hIdx, gh1 = h0 + hIdx + 16;

    // prefetch xb for t = 0
    float xb00 = g_buf[(size_t)gb0 * H_ + gh0];
    float xb01 = g_buf[(size_t)gb0 * H_ + gh1];
    float xb10 = g_buf[(size_t)gb1 * H_ + gh0];
    float xb11 = g_buf[(size_t)gb1 * H_ + gh1];

    for (int t = 0; t < T_; ++t) {
        float* cur = g_buf + (size_t)t * B_ * H_;

        unsigned long long accA = 0ull, accB = 0ull;  // (a00,a01), (a10,a11)

        if (t > 0) {
            const float* sp = g_buf + (size_t)(t - 1) * B_ * H_ + (size_t)b0 * H_;

            // preload chunk 0 into registers
            float4 pv[4];
#pragma unroll
            for (int it = 0; it < 4; it++) {
                int idx = it * 128 + tid;
                int row = idx >> 5, q = idx & 31;
                pv[it] = *reinterpret_cast<const float4*>(
                    &sp[(size_t)row * H_ + q * 4]);
            }

            for (int c = 0; c < H_ / KC; ++c) {
                float* sb = sS + (c & 1) * (BT * SROW);
                __syncthreads();
#pragma unroll
                for (int it = 0; it < 4; it++) {
                    int idx = it * 128 + tid;
                    int row = idx >> 5, q = idx & 31;
                    *reinterpret_cast<float4*>(&sb[row * SROW + q * 4]) = pv[it];
                }
                __syncthreads();
                if (c + 1 < H_ / KC) {
                    const float* spn = sp + (c + 1) * KC;
#pragma unroll
                    for (int it = 0; it < 4; it++) {
                        int idx = it * 128 + tid;
                        int row = idx >> 5, q = idx & 31;
                        pv[it] = *reinterpret_cast<const float4*>(
                            &spn[(size_t)row * H_ + q * 4]);
                    }
                }
                const float* s0r = &sb[bIdx * SROW];
                const float* s1r = &sb[(bIdx + 8) * SROW];
                const float* wr  = wRow + c * (KC * 2);
#pragma unroll 8
                for (int q = 0; q < KC / 4; q++) {
                    float4 s0 = *reinterpret_cast<const float4*>(&s0r[q * 4]);
                    float4 s1 = *reinterpret_cast<const float4*>(&s1r[q * 4]);
                    ulonglong2 wa = *reinterpret_cast<const ulonglong2*>(&wr[q * 8]);
                    ulonglong2 wb = *reinterpret_cast<const ulonglong2*>(&wr[q * 8 + 4]);
                    fma2(accA, pk2(s0.x), wa.x); fma2(accB, pk2(s1.x), wa.x);
                    fma2(accA, pk2(s0.y), wa.y); fma2(accB, pk2(s1.y), wa.y);
                    fma2(accA, pk2(s0.z), wb.x); fma2(accB, pk2(s1.z), wb.x);
                    fma2(accA, pk2(s0.w), wb.y); fma2(accB, pk2(s1.w), wb.y);
                }
            }
        }

        // epilogue: s_t = tanh(xb + acc), in place
        float2 rA = unpk(accA);
        float2 rB = unpk(accB);
        cur[(size_t)gb0 * H_ + gh0] = tanhf(xb00 + rA.x);
        cur[(size_t)gb0 * H_ + gh1] = tanhf(xb01 + rA.y);
        cur[(size_t)gb1 * H_ + gh0] = tanhf(xb10 + rB.x);
        cur[(size_t)gb1 * H_ + gh1] = tanhf(xb11 + rB.y);

        // prefetch next step's xb BEFORE the barrier (overlaps barrier wait)
        {
            const float* nxt = g_buf + (size_t)((t + 1 < T_) ? t + 1 : t) * B_ * H_;
            xb00 = nxt[(size_t)gb0 * H_ + gh0];
            xb01 = nxt[(size_t)gb0 * H_ + gh1];
            xb10 = nxt[(size_t)gb1 * H_ + gh0];
            xb11 = nxt[(size_t)gb1 * H_ + gh1];
        }

        gsync(base + (++bar));
    }
}

// ---------------------------------------------------------------------------
// Kernel 3: out[b][t][o] = bout[o] + sum_h buf[t][b][h] * Wout[h][o]
// Ping-pong smem, one __syncthreads per k-iter.
// ---------------------------------------------------------------------------
__global__ __launch_bounds__(256) void k_out(const float* __restrict__ Wout,
                                             const float* __restrict__ bout,
                                             float* __restrict__ out) {
    const int BM = 128, BN = 128, BK = 8, NC = H_ / BK;
    __shared__ float As[2][BK][BM + 4];
    __shared__ float Bs[2][BK][BN];

    int tid = threadIdx.x;
    int tx = tid % 16, ty = tid / 16;
    int n0 = blockIdx.x * BN;
    int m0 = blockIdx.y * BM;

    const float* A = g_buf;  // [m][k], m = t*B + b, K = H_

    const int mm = tid >> 1;
    const int kq = (tid & 1) * 4;
    const int lk = tid >> 5;
    const int lq = (tid & 31) * 4;

    float4 ra = *reinterpret_cast<const float4*>(&A[(size_t)(m0 + mm) * H_ + kq]);
    float4 rb = *reinterpret_cast<const float4*>(&Wout[(size_t)lk * O_ + n0 + lq]);
    As[0][kq + 0][mm] = ra.x;
    As[0][kq + 1][mm] = ra.y;
    As[0][kq + 2][mm] = ra.z;
    As[0][kq + 3][mm] = ra.w;
    *reinterpret_cast<float4*>(&Bs[0][lk][lq]) = rb;
    __syncthreads();

    float acc[8][8];
#pragma unroll
    for (int i = 0; i < 8; i++)
#pragma unroll
        for (int j = 0; j < 8; j++) acc[i][j] = 0.f;

    for (int c = 0; c < NC; ++c) {
        int cur = c & 1;
        if (c + 1 < NC) {
            ra = *reinterpret_cast<const float4*>(
                &A[(size_t)(m0 + mm) * H_ + (c + 1) * BK + kq]);
            rb = *reinterpret_cast<const float4*>(
                &Wout[(size_t)((c + 1) * BK + lk) * O_ + n0 + lq]);
        }
#pragma unroll
        for (int k = 0; k < BK; k++) {
            float va[8], vb[8];
#pragma unroll
            for (int i = 0; i < 8; i++) va[i] = As[cur][k][ty + 16 * i];
#pragma unroll
            for (int j = 0; j < 8; j++) vb[j] = Bs[cur][k][tx + 16 * j];
#pragma unroll
            for (int i = 0; i < 8; i++)
#pragma unroll
                for (int j = 0; j < 8; j++) acc[i][j] += va[i] * vb[j];
        }
        if (c + 1 < NC) {
            As[1 - cur][kq + 0][mm] = ra.x;
            As[1 - cur][kq + 1][mm] = ra.y;
            As[1 - cur][kq + 2][mm] = ra.z;
            As[1 - cur][kq + 3][mm] = ra.w;
            *reinterpret_cast<float4*>(&Bs[1 - cur][lk][lq]) = rb;
            __syncthreads();
        }
    }

    // m = t*B + b  ->  out[(b*T + t)*O + n]
#pragma unroll
    for (int i = 0; i < 8; i++) {
        int m = m0 + ty + 16 * i;
        int t = m >> 6;          // / B_
        int b = m & 63;          // % B_
        float* dst = out + ((size_t)b * T_ + t) * O_ + n0;
#pragma unroll
        for (int j = 0; j < 8; j++) {
            int n = tx + 16 * j;
            dst[n] = acc[i][j] + bout[n0 + n];
        }
    }
}

extern "C" void kernel_launch(void* const* d_in, const int* in_sizes, int n_in,
                              void* d_out, int out_size) {
    const float* x    = (const float*)d_in[0];
    const float* Wx   = (const float*)d_in[1];
    const float* Wh   = (const float*)d_in[2];
    const float* bias = (const float*)d_in[3];
    const float* Wout = (const float*)d_in[4];
    const float* bout = (const float*)d_in[5];
    float* out = (float*)d_out;

    (void)in_sizes; (void)n_in; (void)out_size;

    cudaFuncSetAttribute(k_rnn, cudaFuncAttributeMaxDynamicSharedMemorySize,
                         SMEM_RNN);

    dim3 g1(H_ / 128, (B_ * T_) / 128);   // (8, 512)
    k_xw<<<g1, 256>>>(x, Wx, bias);

    k_rnn<<<NB, 128, SMEM_RNN>>>(Wh);     // single persistent launch

    dim3 g3(O_ / 128, (B_ * T_) / 128);   // (4, 512)
    k_out<<<g3, 256>>>(Wout, bout, out);
}